// round 12
// baseline (speedup 1.0000x reference)
#include <cuda_runtime.h>
#include <cstdint>
#include <math.h>

// ---------------------------------------------------------------------------
// Problem dims
// ---------------------------------------------------------------------------
#define B_DIM 32
#define T_DIM 512
#define K_DIM 1024
#define N_DIM 1024
#define M_DIM (B_DIM * T_DIM)   // 16384

// ---------------------------------------------------------------------------
// Static device scratch (allocation-guard safe)
// ---------------------------------------------------------------------------
__device__ float g_Y[(size_t)M_DIM * N_DIM];   // 64 MB pre-activations

// ---------------------------------------------------------------------------
// SGEMM: Y[m][n] = sum_k X[m][k] * W[n][k]   (serial-k fp32, bitwise-exact)
// 128x64 tile (2048 CTAs: smooth waves), BK=16, 256 threads, 8x4 per thread
// via fma.rn.f32x2 with row-paired accumulators (R8 scheme, halved N).
// Light registers (~75) -> 3 CTAs/SM. Static smem 25.6 KB.
// ---------------------------------------------------------------------------
#define BM 128
#define BN 64
#define BK 16
#define PADA 132   // A row stride in floats (128 m + 4)
#define PADB 68    // B row stride in floats (64 n + 4)

__global__ void __launch_bounds__(256, 3)
gemm_kernel(const float* __restrict__ A,      // [M_DIM, K_DIM]
            const float* __restrict__ W)      // [N_DIM, K_DIM]
{
    __shared__ float As[2][BK][PADA];
    __shared__ float Bs[2][BK][PADB];

    const int bm = blockIdx.y * BM;
    const int bn = blockIdx.x * BN;
    const int tid = threadIdx.x;

    // A load mapping: 512 float4 per chunk; thread does v = tid and tid+256
    const int ar0 = tid >> 2;               // 0..63   (row of first A vec)
    const int ak  = (tid & 3) << 2;         // 0,4,8,12 (k offset)
    // W load mapping: 256 float4 per chunk; row 0..63
    const int wr  = tid >> 2;               // 0..63
    const int wk  = (tid & 3) << 2;

    // compute mapping: 16x16 threads, 8 rows x 4 cols each
    const int ty = tid >> 4;                // 0..15
    const int tx = tid & 15;                // 0..15

    const float* Ab = A + (size_t)bm * K_DIM;
    const float* Wb = W + (size_t)bn * K_DIM;

    // row-paired accumulators: acc2[ip][j]
    // ip=0: rows (4ty, 4ty+1); ip=1: (4ty+2, 4ty+3);
    // ip=2: (64+4ty, +1);      ip=3: (64+4ty+2, +3). col j: tx*4 + j.
    unsigned long long acc2[4][4];
#pragma unroll
    for (int ip = 0; ip < 4; ip++)
#pragma unroll
        for (int j = 0; j < 4; j++) acc2[ip][j] = 0ULL;

    float4 sa0, sa1, sw0;

    auto ldg_chunk = [&](int k0) {
        sa0 = *(const float4*)(Ab + (size_t)ar0        * K_DIM + k0 + ak);
        sa1 = *(const float4*)(Ab + (size_t)(ar0 + 64) * K_DIM + k0 + ak);
        sw0 = *(const float4*)(Wb + (size_t)wr         * K_DIM + k0 + wk);
    };

    auto sts_chunk = [&](int buf) {
        As[buf][ak + 0][ar0]      = sa0.x; As[buf][ak + 1][ar0]      = sa0.y;
        As[buf][ak + 2][ar0]      = sa0.z; As[buf][ak + 3][ar0]      = sa0.w;
        As[buf][ak + 0][ar0 + 64] = sa1.x; As[buf][ak + 1][ar0 + 64] = sa1.y;
        As[buf][ak + 2][ar0 + 64] = sa1.z; As[buf][ak + 3][ar0 + 64] = sa1.w;
        Bs[buf][wk + 0][wr] = sw0.x; Bs[buf][wk + 1][wr] = sw0.y;
        Bs[buf][wk + 2][wr] = sw0.z; Bs[buf][wk + 3][wr] = sw0.w;
    };

    // prologue
    ldg_chunk(0);
    sts_chunk(0);
    __syncthreads();

    const int NCHUNK = K_DIM / BK;      // 64
    for (int c = 0; c < NCHUNK; c++) {
        const int buf = c & 1;
        if (c + 1 < NCHUNK) ldg_chunk((c + 1) * BK);

#pragma unroll
        for (int kk = 0; kk < BK; kk++) {
            ulonglong2 ap0 = *(const ulonglong2*)&As[buf][kk][4 * ty];
            ulonglong2 ap1 = *(const ulonglong2*)&As[buf][kk][64 + 4 * ty];
            float4 bv = *(const float4*)&Bs[buf][kk][4 * tx];

            unsigned long long a2[4] = {ap0.x, ap0.y, ap1.x, ap1.y};

            unsigned long long b2[4];
            asm("mov.b64 %0, {%1,%1};" : "=l"(b2[0]) : "f"(bv.x));
            asm("mov.b64 %0, {%1,%1};" : "=l"(b2[1]) : "f"(bv.y));
            asm("mov.b64 %0, {%1,%1};" : "=l"(b2[2]) : "f"(bv.z));
            asm("mov.b64 %0, {%1,%1};" : "=l"(b2[3]) : "f"(bv.w));

#pragma unroll
            for (int ip = 0; ip < 4; ip++)
#pragma unroll
                for (int j = 0; j < 4; j++)
                    asm("fma.rn.f32x2 %0, %1, %2, %0;"
                        : "+l"(acc2[ip][j]) : "l"(a2[ip]), "l"(b2[j]));
        }

        if (c + 1 < NCHUNK) sts_chunk(buf ^ 1);
        __syncthreads();
    }

    // epilogue: unpack row-pairs, one float4 store per row
#pragma unroll
    for (int ip = 0; ip < 4; ip++) {
        const int rbase = bm + ((ip < 2) ? (4 * ty + 2 * ip) : (64 + 4 * ty + 2 * (ip - 2)));
        float lo[4], hi[4];
#pragma unroll
        for (int j = 0; j < 4; j++)
            asm("mov.b64 {%0,%1}, %2;" : "=f"(lo[j]), "=f"(hi[j]) : "l"(acc2[ip][j]));
        const int ccol = bn + 4 * tx;
        *(float4*)(g_Y + (size_t)rbase * N_DIM + ccol) =
            make_float4(lo[0], lo[1], lo[2], lo[3]);
        *(float4*)(g_Y + (size_t)(rbase + 1) * N_DIM + ccol) =
            make_float4(hi[0], hi[1], hi[2], hi[3]);
    }
}

// ---------------------------------------------------------------------------
// Membrane scan with fused bias. 1 float/thread (32768 threads), unroll 16.
// ---------------------------------------------------------------------------
__global__ void __launch_bounds__(256)
scan_kernel(const float* __restrict__ bias, float* __restrict__ out)
{
    const int idx = blockIdx.x * blockDim.x + threadIdx.x;   // 0..32767
    const int b = idx >> 10;
    const int n = idx & 1023;

    const float* yp = g_Y + ((size_t)b * T_DIM) * N_DIM + n;
    float* op = out + (size_t)b * N_DIM + n;
    const float bv = bias[n];

    const float f = (float)exp(-0.01);
    const float omf = 1.0f - f;

    float v = 0.0f;

    for (int t = 0; t < T_DIM; t += 16) {
        float y[16];
#pragma unroll
        for (int j = 0; j < 16; j++)
            y[j] = yp[(size_t)(t + j) * N_DIM];
#pragma unroll
        for (int j = 0; j < 16; j++) {
            float yy = y[j] + bv;
            v = f * v + omf * yy;
            float s = (v >= 1.0f) ? 1.0f : 0.0f;
            v = (s != 0.0f) ? 0.0f : v;
            op[(size_t)(t + j) * ((size_t)B_DIM * N_DIM)] = s;
        }
    }
}

// ---------------------------------------------------------------------------
extern "C" void kernel_launch(void* const* d_in, const int* in_sizes, int n_in,
                              void* d_out, int out_size)
{
    const float* x    = (const float*)d_in[0];   // [B, T, 1024]
    const float* W    = (const float*)d_in[1];   // [1024, 1024]
    const float* bias = (const float*)d_in[2];   // [1024]
    float* out        = (float*)d_out;           // [T, B, 1024]

    dim3 grid(N_DIM / BN, M_DIM / BM);           // (16, 128) = 2048 CTAs
    gemm_kernel<<<grid, 256>>>(x, W);

    scan_kernel<<<(B_DIM * N_DIM) / 256, 256>>>(bias, out);
}

// round 15
// speedup vs baseline: 1.1557x; 1.1557x over previous
#include <cuda_runtime.h>
#include <cstdint>
#include <math.h>

// ---------------------------------------------------------------------------
// Problem dims
// ---------------------------------------------------------------------------
#define B_DIM 32
#define T_DIM 512
#define K_DIM 1024
#define N_DIM 1024
#define M_DIM (B_DIM * T_DIM)   // 16384

// ---------------------------------------------------------------------------
// Static device scratch (allocation-guard safe)
// ---------------------------------------------------------------------------
__device__ float g_Y[(size_t)M_DIM * N_DIM];   // 64 MB pre-activations

// ---------------------------------------------------------------------------
// SGEMM (R8 config, proven 599us): Y[m][n] = sum_k X[m][k] * W[n][k]
// 128x128 tile, BK=16, 256 threads, 8x8 per thread via fma.rn.f32x2 with
// row-paired accumulators. Serial-k fp32 -> bitwise-exact vs reference.
// ---------------------------------------------------------------------------
#define BM 128
#define BN 128
#define BK 16
#define PAD 132    // row stride in floats

__global__ void __launch_bounds__(256, 2)
gemm_kernel(const float* __restrict__ A,      // [M_DIM, K_DIM]
            const float* __restrict__ W)      // [N_DIM, K_DIM]
{
    __shared__ float As[2][BK][PAD];
    __shared__ float Bs[2][BK][PAD];

    const int bm = blockIdx.y * BM;
    const int bn = blockIdx.x * BN;
    const int tid = threadIdx.x;

    // load mapping: 256 threads, each 2 float4 from A and 2 from W per chunk
    const int lr = tid >> 2;            // 0..63
    const int lc = (tid & 3) << 2;      // 0,4,8,12

    // compute mapping: 16x16 threads, 8x8 each
    const int ty = tid >> 4;            // 0..15
    const int tx = tid & 15;            // 0..15

    const float* Ab = A + (size_t)bm * K_DIM;
    const float* Wb = W + (size_t)bn * K_DIM;

    // row-paired accumulators:
    // ip=0: rows (ty*4, ty*4+1)   ip=1: (ty*4+2, ty*4+3)
    // ip=2: (64+ty*4, +1)         ip=3: (64+ty*4+2, +3)
    // j<4: col tx*4+j ; j>=4: col 64+tx*4+(j-4)
    unsigned long long acc2[4][8];
#pragma unroll
    for (int ip = 0; ip < 4; ip++)
#pragma unroll
        for (int j = 0; j < 8; j++) acc2[ip][j] = 0ULL;

    float4 a0, a1, w0, w1;

    auto ldg_chunk = [&](int k0) {
        a0 = *(const float4*)(Ab + (size_t)lr        * K_DIM + k0 + lc);
        a1 = *(const float4*)(Ab + (size_t)(lr + 64) * K_DIM + k0 + lc);
        w0 = *(const float4*)(Wb + (size_t)lr        * K_DIM + k0 + lc);
        w1 = *(const float4*)(Wb + (size_t)(lr + 64) * K_DIM + k0 + lc);
    };

    auto sts_chunk = [&](int buf) {
        As[buf][lc + 0][lr]      = a0.x; As[buf][lc + 1][lr]      = a0.y;
        As[buf][lc + 2][lr]      = a0.z; As[buf][lc + 3][lr]      = a0.w;
        As[buf][lc + 0][lr + 64] = a1.x; As[buf][lc + 1][lr + 64] = a1.y;
        As[buf][lc + 2][lr + 64] = a1.z; As[buf][lc + 3][lr + 64] = a1.w;
        Bs[buf][lc + 0][lr]      = w0.x; Bs[buf][lc + 1][lr]      = w0.y;
        Bs[buf][lc + 2][lr]      = w0.z; Bs[buf][lc + 3][lr]      = w0.w;
        Bs[buf][lc + 0][lr + 64] = w1.x; Bs[buf][lc + 1][lr + 64] = w1.y;
        Bs[buf][lc + 2][lr + 64] = w1.z; Bs[buf][lc + 3][lr + 64] = w1.w;
    };

    // prologue
    ldg_chunk(0);
    sts_chunk(0);
    __syncthreads();

    const int NCHUNK = K_DIM / BK;      // 64
    for (int c = 0; c < NCHUNK; c++) {
        const int buf = c & 1;
        if (c + 1 < NCHUNK) ldg_chunk((c + 1) * BK);

#pragma unroll
        for (int kk = 0; kk < BK; kk++) {
            // A row-pairs, packed for free (consecutive m adjacent in smem)
            ulonglong2 ap0 = *(const ulonglong2*)&As[buf][kk][4 * ty];
            ulonglong2 ap1 = *(const ulonglong2*)&As[buf][kk][64 + 4 * ty];
            // B columns (scalar values, duplicated into f32x2 operands)
            float4 bv0 = *(const float4*)&Bs[buf][kk][4 * tx];
            float4 bv1 = *(const float4*)&Bs[buf][kk][64 + 4 * tx];

            unsigned long long a2[4] = {ap0.x, ap0.y, ap1.x, ap1.y};

            unsigned long long b2[8];
            asm("mov.b64 %0, {%1,%1};" : "=l"(b2[0]) : "f"(bv0.x));
            asm("mov.b64 %0, {%1,%1};" : "=l"(b2[1]) : "f"(bv0.y));
            asm("mov.b64 %0, {%1,%1};" : "=l"(b2[2]) : "f"(bv0.z));
            asm("mov.b64 %0, {%1,%1};" : "=l"(b2[3]) : "f"(bv0.w));
            asm("mov.b64 %0, {%1,%1};" : "=l"(b2[4]) : "f"(bv1.x));
            asm("mov.b64 %0, {%1,%1};" : "=l"(b2[5]) : "f"(bv1.y));
            asm("mov.b64 %0, {%1,%1};" : "=l"(b2[6]) : "f"(bv1.z));
            asm("mov.b64 %0, {%1,%1};" : "=l"(b2[7]) : "f"(bv1.w));

#pragma unroll
            for (int ip = 0; ip < 4; ip++)
#pragma unroll
                for (int j = 0; j < 8; j++)
                    asm("fma.rn.f32x2 %0, %1, %2, %0;"
                        : "+l"(acc2[ip][j]) : "l"(a2[ip]), "l"(b2[j]));
        }

        if (c + 1 < NCHUNK) sts_chunk(buf ^ 1);
        __syncthreads();
    }

    // epilogue: unpack row-pairs and store float4 per row
#pragma unroll
    for (int ip = 0; ip < 4; ip++) {
        const int rbase = bm + ((ip < 2) ? (ty * 4 + 2 * ip) : (64 + ty * 4 + 2 * (ip - 2)));
        float lo[8], hi[8];
#pragma unroll
        for (int j = 0; j < 8; j++)
            asm("mov.b64 {%0,%1}, %2;" : "=f"(lo[j]), "=f"(hi[j]) : "l"(acc2[ip][j]));
#pragma unroll
        for (int jb = 0; jb < 2; jb++) {
            const int ccol = bn + jb * 64 + tx * 4;
            float4 v0 = make_float4(lo[jb * 4 + 0], lo[jb * 4 + 1], lo[jb * 4 + 2], lo[jb * 4 + 3]);
            float4 v1 = make_float4(hi[jb * 4 + 0], hi[jb * 4 + 1], hi[jb * 4 + 2], hi[jb * 4 + 3]);
            *(float4*)(g_Y + (size_t)rbase * N_DIM + ccol) = v0;
            *(float4*)(g_Y + (size_t)(rbase + 1) * N_DIM + ccol) = v1;
        }
    }
}

// ---------------------------------------------------------------------------
// Membrane scan with fused bias. 1 float/thread (32768 threads), unroll 16.
// 256 blocks x 128 threads: covers all 148 SMs (vs 128 blocks leaving >=20
// idle). Streaming cache ops: g_Y / out lines touched exactly once.
// ---------------------------------------------------------------------------
__global__ void __launch_bounds__(128)
scan_kernel(const float* __restrict__ bias, float* __restrict__ out)
{
    const int idx = blockIdx.x * blockDim.x + threadIdx.x;   // 0..32767
    const int b = idx >> 10;
    const int n = idx & 1023;

    const float* yp = g_Y + ((size_t)b * T_DIM) * N_DIM + n;
    float* op = out + (size_t)b * N_DIM + n;
    const float bv = bias[n];

    const float f = (float)exp(-0.01);
    const float omf = 1.0f - f;

    float v = 0.0f;

    for (int t = 0; t < T_DIM; t += 16) {
        float y[16];
#pragma unroll
        for (int j = 0; j < 16; j++)
            asm("ld.global.cs.f32 %0, [%1];"
                : "=f"(y[j]) : "l"(yp + (size_t)(t + j) * N_DIM));
#pragma unroll
        for (int j = 0; j < 16; j++) {
            float yy = y[j] + bv;
            v = f * v + omf * yy;
            float s = (v >= 1.0f) ? 1.0f : 0.0f;
            v = (s != 0.0f) ? 0.0f : v;
            asm volatile("st.global.cs.f32 [%0], %1;"
                :: "l"(op + (size_t)(t + j) * ((size_t)B_DIM * N_DIM)), "f"(s));
        }
    }
}

// ---------------------------------------------------------------------------
extern "C" void kernel_launch(void* const* d_in, const int* in_sizes, int n_in,
                              void* d_out, int out_size)
{
    const float* x    = (const float*)d_in[0];   // [B, T, 1024]
    const float* W    = (const float*)d_in[1];   // [1024, 1024]
    const float* bias = (const float*)d_in[2];   // [1024]
    float* out        = (float*)d_out;           // [T, B, 1024]

    dim3 grid(N_DIM / BN, M_DIM / BM);           // (8, 128) = 1024 CTAs
    gemm_kernel<<<grid, 256>>>(x, W);

    // 32768 threads as 256 blocks x 128 — full SM coverage
    scan_kernel<<<256, 128>>>(bias, out);
}